// round 7
// baseline (speedup 1.0000x reference)
#include <cuda_runtime.h>
#include <cstdint>

#define HWC 4096
#define NSLICES 8192
#define NPART 32

#define CWG_F  (-2.0f    / 33554432.0f)
#define DCML_F (-0.01f   / 33554432.0f)
#define TV_F   (1.0e-4f  / 16128.0f)
#define RCUT2  324.0f                      // 18^2; truncation ~5.5e-5 rel (measured)

__device__ float    g_partial[NPART];      // zero at load; finalize re-zeroes
__device__ unsigned g_done;                // zero at load; finalize re-zeroes

__device__ __forceinline__ float fsqrt_approx(float x) {
    float y; asm("sqrt.approx.f32 %0, %1;" : "=f"(y) : "f"(x)); return y;
}
__device__ __forceinline__ float fex2(float x) {
    float y; asm("ex2.approx.f32 %0, %1;" : "=f"(y) : "f"(x)); return y;
}

// One block per (b,p) slice. Blocks 0..255 also own one TV/DCML line.
// Last block (ticket) folds g_partial into out — single launch total.
__global__ void __launch_bounds__(256) fused_kernel(
    const float* __restrict__ sim,
    const float* __restrict__ wc,
    const int*  __restrict__ mask,
    float*      __restrict__ out)
{
    const int j   = threadIdx.x;
    const int blk = blockIdx.x;
    float total = 0.0f;

    // ---- TV + DCML: blocks 0..255 each own one row/col line ----
    if (blk < 256) {
        __shared__ float c0[64], c1[64], m[64];
        const int orient = blk >> 7;       // 0: row lines (use x), 1: col lines (use y)
        const int b      = (blk >> 6) & 1;
        const int line   = blk & 63;
        if (j < 64) {
            int p = (orient == 0) ? (b * HWC + line * 64 + j)
                                  : (b * HWC + j * 64 + line);
            c0[j] = wc[2 * p + 0];
            c1[j] = wc[2 * p + 1];
            m[j]  = mask[p] ? 1.0f : 0.0f;
        }
        __syncthreads();
        if (j < 64) {
            float dc = 0.0f;
            const float vj = orient ? c0[j] : c1[j];
            if (m[j] != 0.0f) {
                for (int q = j + 1; q < 64; q++)
                    dc += fmaxf((orient ? c0[q] : c1[q]) - vj, 0.0f) * m[q];
            }
            float tv = 0.0f;
            if (j < 63) {
                const float d0 = c0[j + 1] - c0[j];
                const float d1 = c1[j + 1] - c1[j];
                tv = (d0 * d0 + d1 * d1) * m[j] * m[j + 1];
            }
            total = dc * DCML_F + tv * TV_F;
        }
        __syncthreads();
    }

    // ---- CWG: this block's single slice, disk cutoff, front-batched loads ----
    if (mask[blk]) {
        const float wcy = wc[2 * blk + 0];
        const float wcx = wc[2 * blk + 1];
        const float4* s4 = (const float4*)(sim + (size_t)blk * 4096);
        const float K = -0.72134752044448169f;   // -0.5*log2(e)

        const int toff  = ((j >> 5) << 7) + ((j & 31) << 2);  // elem offset in 1024-chunk
        const float a0  = (float)(toff & 63) - wcx;           // dx of first of 4 cols
        const float dxn = fmaxf(fmaxf(a0, -a0 - 3.0f), 0.0f); // nearest |dx| of the 4
        const float dxn2 = dxn * dxn;

        float4 v[4]; float dy2[4]; bool pr[4];
#pragma unroll
        for (int p = 0; p < 4; p++) {            // predicates + all 4 loads first (MLP=4)
            const float dy = (float)((p * 1024 + toff) >> 6) - wcy;
            dy2[p] = dy * dy;
            pr[p] = (dy2[p] + dxn2) < RCUT2;
            v[p] = pr[p] ? s4[(p * 1024 + toff) >> 2] : make_float4(0.f, 0.f, 0.f, 0.f);
        }
        float cacc = 0.0f;
#pragma unroll
        for (int p = 0; p < 4; p++) {
            if (pr[p]) {
                const float d2 = dy2[p];
                cacc += v[p].x * fex2(K * fsqrt_approx(d2 + a0 * a0));
                cacc += v[p].y * fex2(K * fsqrt_approx(d2 + (a0 + 1.f) * (a0 + 1.f)));
                cacc += v[p].z * fex2(K * fsqrt_approx(d2 + (a0 + 2.f) * (a0 + 2.f)));
                cacc += v[p].w * fex2(K * fsqrt_approx(d2 + (a0 + 3.f) * (a0 + 3.f)));
            }
        }
        total += cacc * CWG_F;
    }

    // ---- block reduce + global accumulate + last-block finalize ----
#pragma unroll
    for (int o = 16; o; o >>= 1) total += __shfl_down_sync(0xffffffffu, total, o);
    __shared__ float sh[8];
    __shared__ bool  s_last;
    if ((j & 31) == 0) sh[j >> 5] = total;
    __syncthreads();
    if (j == 0) {
        float s = 0.0f;
#pragma unroll
        for (int w = 0; w < 8; w++) s += sh[w];
        atomicAdd(&g_partial[blk & (NPART - 1)], s);
        __threadfence();
        const unsigned t = atomicAdd(&g_done, 1u);
        s_last = (t == (unsigned)(NSLICES - 1));
    }
    __syncthreads();
    if (s_last && j < NPART) {
        float v = atomicExch(&g_partial[j], 0.0f);   // read + reset for next replay
#pragma unroll
        for (int o = 16; o; o >>= 1) v += __shfl_down_sync(0xffffffffu, v, o);
        if (j == 0) {
            out[0] = v;
            atomicExch(&g_done, 0u);                 // reset ticket for next replay
        }
    }
}

extern "C" void kernel_launch(void* const* d_in, const int* in_sizes, int n_in,
                              void* d_out, int out_size)
{
    const float* sim  = (const float*)d_in[0];
    const float* wc   = (const float*)d_in[1];
    const int*   mask = (const int*)d_in[2];
    float* out = (float*)d_out;

    fused_kernel<<<NSLICES, 256>>>(sim, wc, mask, out);
}

// round 8
// speedup vs baseline: 1.2351x; 1.2351x over previous
#include <cuda_runtime.h>
#include <cstdint>

#define HWC 4096
#define NSLICES 8192
#define NPART 32
#define NL1 64
#define L1_TARGET (NSLICES / NL1)          // 128

#define CWG_F  (-2.0f    / 33554432.0f)
#define DCML_F (-0.01f   / 33554432.0f)
#define TV_F   (1.0e-4f  / 16128.0f)
#define RCUT2  324.0f                      // 18^2; truncation ~5.5e-5 rel (measured)

__device__ float    g_partial[NPART];      // zero at load; finalizer re-zeroes
__device__ unsigned g_t1[NL1];             // level-1 ticket counters
__device__ unsigned g_t2;                  // level-2 ticket counter

__device__ __forceinline__ float fsqrt_approx(float x) {
    float y; asm("sqrt.approx.f32 %0, %1;" : "=f"(y) : "f"(x)); return y;
}
__device__ __forceinline__ float fex2(float x) {
    float y; asm("ex2.approx.f32 %0, %1;" : "=f"(y) : "f"(x)); return y;
}

// Thread-0-only: arrive at hierarchical ticket; last arrival folds g_partial
// into out and resets all state for the next graph replay.
__device__ __forceinline__ void ticket_and_finalize(int blk, float* __restrict__ out) {
    const unsigned t1 = atomicAdd(&g_t1[blk & (NL1 - 1)], 1u);
    if (t1 == (unsigned)(L1_TARGET - 1)) {
        g_t1[blk & (NL1 - 1)] = 0u;                       // reset own partition
        const unsigned t2 = atomicAdd(&g_t2, 1u);
        if (t2 == (unsigned)(NL1 - 1)) {
            float s = 0.0f;
#pragma unroll
            for (int i = 0; i < NPART; i++)
                s += atomicExch(&g_partial[i], 0.0f);     // read + reset (32 indep atomics)
            out[0] = s;
            atomicExch(&g_t2, 0u);
        }
    }
}

// One block per (b,p) slice. Blocks 0..255 additionally own one TV/DCML line.
// Masked non-TV blocks: ticket only, instant retire.
__global__ void __launch_bounds__(256) fused_kernel(
    const float* __restrict__ sim,
    const float* __restrict__ wc,
    const int*  __restrict__ mask,
    float*      __restrict__ out)
{
    const int j   = threadIdx.x;
    const int blk = blockIdx.x;

    // issue both block-scalar loads immediately (independent; broadcast in L1)
    const int   mk  = mask[blk];
    const float wcy = wc[2 * blk + 0];
    const float wcx = wc[2 * blk + 1];

    const bool tvblk = (blk < 256);
    if (!tvblk && !mk) {                   // fast path: no barriers, no reduce
        if (j == 0) ticket_and_finalize(blk, out);
        return;
    }

    float total = 0.0f;

    // ---- TV + DCML: blocks 0..255 each own one row/col line ----
    if (tvblk) {
        __shared__ float c0[64], c1[64], m[64];
        const int orient = blk >> 7;       // 0: row lines (use x), 1: col lines (use y)
        const int b      = (blk >> 6) & 1;
        const int line   = blk & 63;
        if (j < 64) {
            int p = (orient == 0) ? (b * HWC + line * 64 + j)
                                  : (b * HWC + j * 64 + line);
            c0[j] = wc[2 * p + 0];
            c1[j] = wc[2 * p + 1];
            m[j]  = mask[p] ? 1.0f : 0.0f;
        }
        __syncthreads();
        if (j < 64) {
            float dc = 0.0f;
            const float vj = orient ? c0[j] : c1[j];
            if (m[j] != 0.0f) {
                for (int q = j + 1; q < 64; q++)
                    dc += fmaxf((orient ? c0[q] : c1[q]) - vj, 0.0f) * m[q];
            }
            float tv = 0.0f;
            if (j < 63) {
                const float d0 = c0[j + 1] - c0[j];
                const float d1 = c1[j + 1] - c1[j];
                tv = (d0 * d0 + d1 * d1) * m[j] * m[j + 1];
            }
            total = dc * DCML_F + tv * TV_F;
        }
        __syncthreads();
    }

    // ---- CWG: this block's slice, disk cutoff, front-batched loads ----
    if (mk) {
        const float4* s4 = (const float4*)(sim + (size_t)blk * 4096);
        const float K = -0.72134752044448169f;   // -0.5*log2(e)

        const int toff  = ((j >> 5) << 7) + ((j & 31) << 2);  // elem offset in 1024-chunk
        const float a0  = (float)(toff & 63) - wcx;           // dx of first of 4 cols
        const float dxn = fmaxf(fmaxf(a0, -a0 - 3.0f), 0.0f); // nearest |dx| of the 4
        const float dxn2 = dxn * dxn;

        float4 v[4]; float dy2[4]; bool pr[4];
#pragma unroll
        for (int p = 0; p < 4; p++) {            // predicates + all 4 loads first (MLP=4)
            const float dy = (float)((p * 1024 + toff) >> 6) - wcy;
            dy2[p] = dy * dy;
            pr[p] = (dy2[p] + dxn2) < RCUT2;
            v[p] = pr[p] ? s4[(p * 1024 + toff) >> 2] : make_float4(0.f, 0.f, 0.f, 0.f);
        }
        float cacc = 0.0f;
#pragma unroll
        for (int p = 0; p < 4; p++) {
            if (pr[p]) {
                const float d2 = dy2[p];
                cacc += v[p].x * fex2(K * fsqrt_approx(d2 + a0 * a0));
                cacc += v[p].y * fex2(K * fsqrt_approx(d2 + (a0 + 1.f) * (a0 + 1.f)));
                cacc += v[p].z * fex2(K * fsqrt_approx(d2 + (a0 + 2.f) * (a0 + 2.f)));
                cacc += v[p].w * fex2(K * fsqrt_approx(d2 + (a0 + 3.f) * (a0 + 3.f)));
            }
        }
        total += cacc * CWG_F;
    }

    // ---- block reduce + global accumulate + ticket ----
#pragma unroll
    for (int o = 16; o; o >>= 1) total += __shfl_down_sync(0xffffffffu, total, o);
    __shared__ float sh[8];
    if ((j & 31) == 0) sh[j >> 5] = total;
    __syncthreads();
    if (j == 0) {
        float s = 0.0f;
#pragma unroll
        for (int w = 0; w < 8; w++) s += sh[w];
        atomicAdd(&g_partial[blk & (NPART - 1)], s);
        __threadfence();                     // publish before ticket arrival
        ticket_and_finalize(blk, out);
    }
}

extern "C" void kernel_launch(void* const* d_in, const int* in_sizes, int n_in,
                              void* d_out, int out_size)
{
    const float* sim  = (const float*)d_in[0];
    const float* wc   = (const float*)d_in[1];
    const int*   mask = (const int*)d_in[2];
    float* out = (float*)d_out;

    fused_kernel<<<NSLICES, 256>>>(sim, wc, mask, out);
}